// round 9
// baseline (speedup 1.0000x reference)
#include <cuda_runtime.h>
#include <cuda_bf16.h>
#include <math.h>
#include <stdint.h>

// Problem dims
#define B_ 32
#define T_ 64
#define P_ 10
#define I_ 1024
#define H_ 1024
#define C_ 8
#define G4 4096
#define M_ (B_*T_*P_)     // 20480

// Scratch (device globals; no allocation allowed)
__device__ float d_xwx[(size_t)T_*B_*P_*H_];   // 80 MB: x@Wx^T, layout [t][b][p][h]
__device__ float d_pA[4*B_*G4];                // h@Whh^T partials [ks][b][n]
__device__ float d_pC[2*B_*G4];                // emb@Wih^T partials [ks][b][n]
__device__ float d_scores[B_*P_];              // attention scores (atomic accum)
__device__ float d_emb[B_*H_];                 // attention-pooled features
__device__ float d_h[B_*H_];                   // LSTM hidden
__device__ float d_c[B_*H_];                   // LSTM cell

__device__ __forceinline__ float tanh_fast(float x) {
    float y; asm("tanh.approx.f32 %0, %1;" : "=f"(y) : "f"(x)); return y;
}
__device__ __forceinline__ float sigmoidf(float x) {
    return 1.0f / (1.0f + expf(-x));
}

// ---------------------------------------------------------------------------
// zero initial state
// ---------------------------------------------------------------------------
__global__ void zero_state() {
    int i0 = blockIdx.x * 256 + threadIdx.x;
    for (int i = i0; i < B_*H_; i += 128*256) { d_h[i] = 0.0f; d_c[i] = 0.0f; }
    if (i0 < B_*P_) d_scores[i0] = 0.0f;
}

// ---------------------------------------------------------------------------
// sgemm_xwx: xwx[t,b,p,h] = sum_i x[b,t,p,i]*Wx[h,i]
// 128x128 tile, BK=8, 256 threads, 8x8 microtile.
// Double-buffered smem (ping-pong): ONE __syncthreads per k-tile.
// ---------------------------------------------------------------------------
__global__ __launch_bounds__(256, 2) void sgemm_xwx(
    const float* __restrict__ A, const float* __restrict__ Bm)
{
    __shared__ float As[2][8][128];
    __shared__ float Bs[2][8][128];
    const int tid = threadIdx.x;
    const int m0 = blockIdx.y * 128;
    const int n0 = blockIdx.x * 128;
    const int tx = tid & 15;
    const int ty = tid >> 4;

    float acc[8][8];
#pragma unroll
    for (int i = 0; i < 8; i++)
#pragma unroll
        for (int j = 0; j < 8; j++) acc[i][j] = 0.0f;

    const int ar = tid >> 1;
    const int ac = (tid & 1) * 4;
    const float* Aptr = A  + (size_t)(m0 + ar) * I_ + ac;
    const float* Bptr = Bm + (size_t)(n0 + ar) * I_ + ac;

    // prologue: fill buffer 0
    {
        float4 av = *(const float4*)(Aptr);
        float4 bv = *(const float4*)(Bptr);
        As[0][ac+0][ar] = av.x; As[0][ac+1][ar] = av.y;
        As[0][ac+2][ar] = av.z; As[0][ac+3][ar] = av.w;
        Bs[0][ac+0][ar] = bv.x; Bs[0][ac+1][ar] = bv.y;
        Bs[0][ac+2][ar] = bv.z; Bs[0][ac+3][ar] = bv.w;
    }
    __syncthreads();

    int pb = 0;
    for (int kb = 0; kb < I_; kb += 8) {
        const bool has_next = (kb + 8 < I_);
        float4 av_n, bv_n;
        if (has_next) {
            av_n = *(const float4*)(Aptr + kb + 8);
            bv_n = *(const float4*)(Bptr + kb + 8);
        }
#pragma unroll
        for (int kk = 0; kk < 8; kk++) {
            float a_f[8], b_f[8];
            *(float4*)(a_f)     = *(const float4*)&As[pb][kk][ty*8];
            *(float4*)(a_f + 4) = *(const float4*)&As[pb][kk][ty*8 + 4];
            *(float4*)(b_f)     = *(const float4*)&Bs[pb][kk][tx*8];
            *(float4*)(b_f + 4) = *(const float4*)&Bs[pb][kk][tx*8 + 4];
#pragma unroll
            for (int i = 0; i < 8; i++)
#pragma unroll
                for (int j = 0; j < 8; j++)
                    acc[i][j] += a_f[i] * b_f[j];
        }
        if (has_next) {
            int nb = pb ^ 1;
            As[nb][ac+0][ar] = av_n.x; As[nb][ac+1][ar] = av_n.y;
            As[nb][ac+2][ar] = av_n.z; As[nb][ac+3][ar] = av_n.w;
            Bs[nb][ac+0][ar] = bv_n.x; Bs[nb][ac+1][ar] = bv_n.y;
            Bs[nb][ac+2][ar] = bv_n.z; Bs[nb][ac+3][ar] = bv_n.w;
            __syncthreads();
            pb = nb;
        }
    }

    // permuted write: row r=(b*T+t)*P+p -> out row ((t*B+b)*P+p)
#pragma unroll
    for (int i = 0; i < 8; i++) {
        int r   = m0 + ty*8 + i;
        int b   = r / (T_*P_);
        int rem = r % (T_*P_);
        int t   = rem / P_;
        int p   = rem % P_;
        float* o = d_xwx + (size_t)((t*B_ + b)*P_ + p) * H_ + n0 + tx*8;
        *(float4*)(o)     = *(float4*)&acc[i][0];
        *(float4*)(o + 4) = *(float4*)&acc[i][4];
    }
}

// ---------------------------------------------------------------------------
// kh: fused  h @ [Wh | Whh]^T
//   blocks 0..15   : attention rows, FULL K (64n x 32b x 1024k),
//                    fused score epilogue (tanh + v-dot) -> atomicAdd d_scores
//   blocks 16..271 : gate rows, split-K(4) (64n x 32b x 256k) -> d_pA
// 256 threads, microtile 2b x 4n (proven R5 geometry).
// ---------------------------------------------------------------------------
__global__ __launch_bounds__(256) void kh(
    int t, const float* __restrict__ Wh, const float* __restrict__ Whh,
    const float* __restrict__ b_att, const float* __restrict__ v)
{
    __shared__ float u_s[64][32];   // [k][b]
    __shared__ float w_s[64][64];   // [k][n_local]  (reused as red[] in att epilogue)

    const int tid = threadIdx.x;
    const int blk = blockIdx.x;
    const bool att = (blk < 16);
    const int g    = blk - 16;
    const int n0   = att ? blk * 64 : (g & 63) * 64;
    const int ks   = att ? 0 : (g >> 6);
    const int kbeg = att ? 0 : ks * 256;
    const int kend = att ? 1024 : kbeg + 256;
    const float* __restrict__ W = att ? Wh : Whh;

    const int tn = tid & 15;        // 4 n each
    const int tb = tid >> 4;        // 2 b each

    float acc[2][4] = {{0,0,0,0},{0,0,0,0}};

    for (int kb = kbeg; kb < kend; kb += 64) {
        // u tile: 32b x 64k, coalesced float4 LDG, transpose into [k][b]
#pragma unroll
        for (int l = tid*4; l < 2048; l += 1024) {
            int b  = l >> 6;
            int i0 = l & 63;
            float4 uv = *(const float4*)&d_h[b * H_ + kb + i0];
            u_s[i0+0][b] = uv.x; u_s[i0+1][b] = uv.y;
            u_s[i0+2][b] = uv.z; u_s[i0+3][b] = uv.w;
        }
        // w tile: 64 rows x 64 k
#pragma unroll
        for (int l = tid; l < 1024; l += 256) {
            int r = l >> 4;
            int q = (l & 15) * 4;
            float4 wv = *(const float4*)&W[(size_t)(n0 + r) * 1024 + kb + q];
            w_s[q+0][r] = wv.x; w_s[q+1][r] = wv.y;
            w_s[q+2][r] = wv.z; w_s[q+3][r] = wv.w;
        }
        __syncthreads();
#pragma unroll
        for (int i = 0; i < 64; i++) {
            float2 uu = *(const float2*)&u_s[i][tb*2];
            float4 ww = *(const float4*)&w_s[i][tn*4];
            acc[0][0] += uu.x*ww.x; acc[0][1] += uu.x*ww.y;
            acc[0][2] += uu.x*ww.z; acc[0][3] += uu.x*ww.w;
            acc[1][0] += uu.y*ww.x; acc[1][1] += uu.y*ww.y;
            acc[1][2] += uu.y*ww.z; acc[1][3] += uu.y*ww.w;
        }
        __syncthreads();
    }

    if (!att) {
        // gate rows: store split-K partials
#pragma unroll
        for (int bb = 0; bb < 2; bb++) {
            int b = tb*2 + bb;
#pragma unroll
            for (int nn = 0; nn < 4; nn++)
                d_pA[(size_t)(ks*B_ + b)*G4 + n0 + tn*4 + nn] = acc[bb][nn];
        }
        return;
    }

    // ---- attention epilogue: full a[n][b] available in this block ----
    float* red = &w_s[0][0];        // [64][stride 33]
#pragma unroll
    for (int nn = 0; nn < 4; nn++)
#pragma unroll
        for (int bb = 0; bb < 2; bb++)
            red[(tn*4 + nn)*33 + (tb*2 + bb)] = acc[bb][nn];
    __syncthreads();

    // 8 warps x 40 (b,p) items; lane covers 2 n (coalesced xwx reads)
    const int warp = tid >> 5, lane = tid & 31;
    const int n = lane * 2;
    const float ba0 = b_att[n0 + n],   v0 = v[n0 + n];
    const float ba1 = b_att[n0 + n+1], v1 = v[n0 + n+1];
    const float r0a = red[n*33 + 0] - red[n*33 + 0];  // dummy to keep regs tight (optimized out)
    (void)r0a;
    for (int it = warp*40; it < warp*40 + 40; it++) {
        int b = it / P_, p = it % P_;
        const float* xw = d_xwx + (size_t)((t*B_ + b)*P_ + p)*H_ + n0;
        float a0 = xw[n]   + red[n*33 + b]     + ba0;
        float a1 = xw[n+1] + red[(n+1)*33 + b] + ba1;
        float s = v0 * tanh_fast(a0) + v1 * tanh_fast(a1);
#pragma unroll
        for (int o = 16; o; o >>= 1) s += __shfl_xor_sync(0xffffffffu, s, o);
        if (lane == 0) atomicAdd(&d_scores[b*P_ + p], s);
    }
}

// ---------------------------------------------------------------------------
// kge: emb @ Wih^T, split-K(2).  grid (64, 2), 256 threads, chunk 512.
// ---------------------------------------------------------------------------
__global__ __launch_bounds__(256) void kge(const float* __restrict__ Wih)
{
    __shared__ float u_s[64][32];
    __shared__ float w_s[64][64];
    const int tid = threadIdx.x;
    const int n0 = blockIdx.x * 64;
    const int k_start = blockIdx.y * 512;
    const int tn = tid & 15;
    const int tb = tid >> 4;

    float acc[2][4] = {{0,0,0,0},{0,0,0,0}};

    for (int cb = 0; cb < 512; cb += 64) {
        const int kb = k_start + cb;
#pragma unroll
        for (int l = tid*4; l < 2048; l += 1024) {
            int b  = l >> 6;
            int i0 = l & 63;
            float4 uv = *(const float4*)&d_emb[b * H_ + kb + i0];
            u_s[i0+0][b] = uv.x; u_s[i0+1][b] = uv.y;
            u_s[i0+2][b] = uv.z; u_s[i0+3][b] = uv.w;
        }
#pragma unroll
        for (int l = tid; l < 1024; l += 256) {
            int r = l >> 4;
            int q = (l & 15) * 4;
            float4 wv = *(const float4*)&Wih[(size_t)(n0 + r) * 1024 + kb + q];
            w_s[q+0][r] = wv.x; w_s[q+1][r] = wv.y;
            w_s[q+2][r] = wv.z; w_s[q+3][r] = wv.w;
        }
        __syncthreads();
#pragma unroll
        for (int i = 0; i < 64; i++) {
            float2 uu = *(const float2*)&u_s[i][tb*2];
            float4 ww = *(const float4*)&w_s[i][tn*4];
            acc[0][0] += uu.x*ww.x; acc[0][1] += uu.x*ww.y;
            acc[0][2] += uu.x*ww.z; acc[0][3] += uu.x*ww.w;
            acc[1][0] += uu.y*ww.x; acc[1][1] += uu.y*ww.y;
            acc[1][2] += uu.y*ww.z; acc[1][3] += uu.y*ww.w;
        }
        __syncthreads();
    }

    const int ks = blockIdx.y;
#pragma unroll
    for (int bb = 0; bb < 2; bb++) {
        int b = tb*2 + bb;
#pragma unroll
        for (int nn = 0; nn < 4; nn++)
            d_pC[(size_t)(ks*B_ + b)*G4 + n0 + tn*4 + nn] = acc[bb][nn];
    }
}

// ---------------------------------------------------------------------------
// kpool: softmax over P + attention pooling -> d_emb.  grid (8, 32), 128t.
// ---------------------------------------------------------------------------
__global__ __launch_bounds__(128) void kpool(int t, const float* __restrict__ x)
{
    const int b = blockIdx.y;
    const int i = blockIdx.x * 128 + threadIdx.x;

    float sc[P_];
#pragma unroll
    for (int p = 0; p < P_; p++) sc[p] = d_scores[b*P_ + p];
    float mx = sc[0];
#pragma unroll
    for (int p = 1; p < P_; p++) mx = fmaxf(mx, sc[p]);
    float al[P_], ssum = 0.0f;
#pragma unroll
    for (int p = 0; p < P_; p++) { al[p] = expf(sc[p] - mx); ssum += al[p]; }
    float inv = 1.0f / ssum;

    const float* xb = &x[(size_t)((b*T_ + t)*P_) * I_ + i];
    float e = 0.0f;
#pragma unroll
    for (int p = 0; p < P_; p++) e += al[p] * xb[p*I_];
    d_emb[b*H_ + i] = e * inv;
}

// ---------------------------------------------------------------------------
// kcell: gates = 4 pA + 2 pC partials + biases -> cell + hidden.
// Also zeroes d_scores for the next step (safe: kpool already consumed them).
// ---------------------------------------------------------------------------
__global__ __launch_bounds__(256) void kcell(const float* __restrict__ bih,
                                             const float* __restrict__ bhh)
{
    int idx = blockIdx.x * 256 + threadIdx.x;   // 32768
    int b = idx >> 10, j = idx & 1023;
    float g4[4];
#pragma unroll
    for (int g = 0; g < 4; g++) {
        int m = g*H_ + j;
        float s = bih[m] + bhh[m];
#pragma unroll
        for (int ks = 0; ks < 4; ks++) s += d_pA[(size_t)(ks*B_ + b)*G4 + m];
#pragma unroll
        for (int ks = 0; ks < 2; ks++) s += d_pC[(size_t)(ks*B_ + b)*G4 + m];
        g4[g] = s;
    }
    float ig = sigmoidf(g4[0]);
    float fg = sigmoidf(g4[1]);
    float gg = tanhf(g4[2]);
    float og = sigmoidf(g4[3]);
    float cn = fg * d_c[idx] + ig * gg;
    d_c[idx] = cn;
    d_h[idx] = og * tanhf(cn);

    if (blockIdx.x == 0) {
        for (int l = threadIdx.x; l < B_*P_; l += 256) d_scores[l] = 0.0f;
    }
}

// ---------------------------------------------------------------------------
// Final FC
// ---------------------------------------------------------------------------
__global__ __launch_bounds__(256) void kfc(const float* __restrict__ Wfc,
                                           const float* __restrict__ bfc,
                                           float* __restrict__ out)
{
    int b = blockIdx.x;
    int w = threadIdx.x >> 5;
    int lane = threadIdx.x & 31;
    const float* h = &d_h[b*H_];
    float acc = 0.0f;
    for (int i = lane; i < H_; i += 32) acc += h[i] * Wfc[w*H_ + i];
#pragma unroll
    for (int o = 16; o; o >>= 1) acc += __shfl_xor_sync(0xffffffffu, acc, o);
    if (lane == 0) out[b*C_ + w] = acc + bfc[w];
}

// ---------------------------------------------------------------------------
extern "C" void kernel_launch(void* const* d_in, const int* in_sizes, int n_in,
                              void* d_out, int out_size)
{
    const float* x    = (const float*)d_in[0];
    const float* Wx   = (const float*)d_in[1];
    const float* Wh   = (const float*)d_in[2];
    const float* batt = (const float*)d_in[3];
    const float* v    = (const float*)d_in[4];
    const float* Wih  = (const float*)d_in[5];
    const float* Whh  = (const float*)d_in[6];
    const float* bih  = (const float*)d_in[7];
    const float* bhh  = (const float*)d_in[8];
    const float* Wfc  = (const float*)d_in[9];
    const float* bfc  = (const float*)d_in[10];
    float* out = (float*)d_out;

    zero_state<<<128, 256>>>();
    sgemm_xwx<<<dim3(H_/128, M_/128), 256>>>(x, Wx);

    for (int t = 0; t < T_; t++) {
        kh<<<272, 256>>>(t, Wh, Whh, batt, v);
        kpool<<<dim3(8, B_), 128>>>(t, x);
        kge<<<dim3(64, 2), 256>>>(Wih);
        kcell<<<128, 256>>>(bih, bhh);
    }
    kfc<<<32, 256>>>(Wfc, bfc, out);
}

// round 10
// speedup vs baseline: 1.5210x; 1.5210x over previous
#include <cuda_runtime.h>
#include <cuda_bf16.h>
#include <math.h>

// Problem dims
#define B_ 32
#define T_ 64
#define P_ 10
#define I_ 1024
#define H_ 1024
#define C_ 8
#define G4 4096
#define M_ (B_*T_*P_)     // 20480
#define N5 5120           // Wh(1024) + Whh(4096) rows merged

// Scratch (device globals; no allocation allowed)
__device__ float d_xwx[(size_t)T_*B_*P_*H_];   // 80 MB: x@Wx^T, layout [t][b][p][h]
__device__ float d_p5[4*B_*N5];                // split-K(4) partials of h@[Wh|Whh]^T
__device__ float d_gpart[2*B_*G4];             // split-K(2) partials of emb@Wih^T
__device__ float d_scores[B_*P_];              // attention scores
__device__ float d_emb[B_*H_];                 // attention-pooled features
__device__ float d_h[B_*H_];                   // LSTM hidden
__device__ float d_c[B_*H_];                   // LSTM cell

__device__ __forceinline__ float tanh_fast(float x) {
    float y; asm("tanh.approx.f32 %0, %1;" : "=f"(y) : "f"(x)); return y;
}
__device__ __forceinline__ float sigmoidf(float x) {
    return 1.0f / (1.0f + expf(-x));
}

// ---------------------------------------------------------------------------
// zero initial state
// ---------------------------------------------------------------------------
__global__ void zero_state() {
    int i0 = blockIdx.x * 256 + threadIdx.x;
    for (int i = i0; i < B_*H_; i += 128*256) { d_h[i] = 0.0f; d_c[i] = 0.0f; }
}

// ---------------------------------------------------------------------------
// sgemm_xwx: xwx[t,b,p,h] = sum_i x[b,t,p,i]*Wx[h,i]
// 128x128 tile, BK=8, 256 threads, 8x8 microtile, register-prefetch pipeline.
// B-fragment columns split {tx*4, 64+tx*4}: 2-way LDS conflicts (was 4-way
// at stride tx*8).
// ---------------------------------------------------------------------------
__global__ __launch_bounds__(256, 2) void sgemm_xwx(
    const float* __restrict__ A, const float* __restrict__ Bm)
{
    __shared__ float As[8][128];
    __shared__ float Bs[8][128];
    const int tid = threadIdx.x;
    const int m0 = blockIdx.y * 128;
    const int n0 = blockIdx.x * 128;
    const int tx = tid & 15;
    const int ty = tid >> 4;

    float acc[8][8];
#pragma unroll
    for (int i = 0; i < 8; i++)
#pragma unroll
        for (int j = 0; j < 8; j++) acc[i][j] = 0.0f;

    const int ar = tid >> 1;
    const int ac = (tid & 1) * 4;
    const float* Aptr = A  + (size_t)(m0 + ar) * I_ + ac;
    const float* Bptr = Bm + (size_t)(n0 + ar) * I_ + ac;

    float4 av = *(const float4*)(Aptr);
    float4 bv = *(const float4*)(Bptr);

    for (int kb = 0; kb < I_; kb += 8) {
        As[ac+0][ar] = av.x; As[ac+1][ar] = av.y; As[ac+2][ar] = av.z; As[ac+3][ar] = av.w;
        Bs[ac+0][ar] = bv.x; Bs[ac+1][ar] = bv.y; Bs[ac+2][ar] = bv.z; Bs[ac+3][ar] = bv.w;
        __syncthreads();

        // prefetch next k-tile into registers (overlaps with FFMA block)
        float4 av_n = av, bv_n = bv;
        if (kb + 8 < I_) {
            av_n = *(const float4*)(Aptr + kb + 8);
            bv_n = *(const float4*)(Bptr + kb + 8);
        }
#pragma unroll
        for (int kk = 0; kk < 8; kk++) {
            float a_f[8], b_f[8];
            *(float4*)(a_f)     = *(const float4*)&As[kk][ty*8];
            *(float4*)(a_f + 4) = *(const float4*)&As[kk][ty*8 + 4];
            *(float4*)(b_f)     = *(const float4*)&Bs[kk][tx*4];        // cols tx*4..+3
            *(float4*)(b_f + 4) = *(const float4*)&Bs[kk][64 + tx*4];   // cols 64+tx*4..+3
#pragma unroll
            for (int i = 0; i < 8; i++)
#pragma unroll
                for (int j = 0; j < 8; j++)
                    acc[i][j] += a_f[i] * b_f[j];
        }
        __syncthreads();
        av = av_n; bv = bv_n;
    }

    // permuted write: row r=(b*T+t)*P+p -> out row ((t*B+b)*P+p)
    // columns: acc[i][0..3] -> n0+tx*4, acc[i][4..7] -> n0+64+tx*4
#pragma unroll
    for (int i = 0; i < 8; i++) {
        int r   = m0 + ty*8 + i;
        int b   = r / (T_*P_);
        int rem = r % (T_*P_);
        int t   = rem / P_;
        int p   = rem % P_;
        float* o = d_xwx + (size_t)((t*B_ + b)*P_ + p) * H_ + n0;
        *(float4*)(o + tx*4)      = *(float4*)&acc[i][0];
        *(float4*)(o + 64 + tx*4) = *(float4*)&acc[i][4];
    }
}

// ---------------------------------------------------------------------------
// Skinny GEMM body: part[ks][b][n0+..] = sum_{k in chunk} U[b][k] * Wrow(n)[k]
// block tile: 64 n x 32 b, 256 threads, microtile 2b x 4n.  (R5 proven)
// ---------------------------------------------------------------------------
template<int CHUNK>
__device__ __forceinline__ void skinny_body(
    const float* __restrict__ U,
    const float* __restrict__ W0, const float* __restrict__ W1,
    int K0, int N, float* __restrict__ part)
{
    __shared__ float u_s[64][32];   // [k][b]
    __shared__ float w_s[64][64];   // [k][n_local]
    const int tid = threadIdx.x;
    const int n0 = blockIdx.x * 64;
    const int k_start = blockIdx.y * CHUNK;
    const int tn = tid & 15;        // 4 n each
    const int tb = tid >> 4;        // 2 b each

    float acc[2][4] = {{0,0,0,0},{0,0,0,0}};

    for (int cb = 0; cb < CHUNK; cb += 64) {
        const int kb = k_start + cb;

#pragma unroll
        for (int l = tid*4; l < 2048; l += 1024) {
            int b  = l >> 6;
            int i0 = l & 63;
            float4 uv = *(const float4*)&U[b * H_ + kb + i0];
            u_s[i0+0][b] = uv.x; u_s[i0+1][b] = uv.y;
            u_s[i0+2][b] = uv.z; u_s[i0+3][b] = uv.w;
        }
#pragma unroll
        for (int l = tid; l < 1024; l += 256) {
            int r = l >> 4;
            int q = (l & 15) * 4;
            int n = n0 + r;
            const float* Wrow = (n < K0) ? (W0 + (size_t)n * 1024)
                                         : (W1 + (size_t)(n - K0) * 1024);
            float4 wv = *(const float4*)&Wrow[kb + q];
            w_s[q+0][r] = wv.x; w_s[q+1][r] = wv.y;
            w_s[q+2][r] = wv.z; w_s[q+3][r] = wv.w;
        }
        __syncthreads();
#pragma unroll
        for (int i = 0; i < 64; i++) {
            float2 uu = *(const float2*)&u_s[i][tb*2];
            float4 ww = *(const float4*)&w_s[i][tn*4];
            acc[0][0] += uu.x*ww.x; acc[0][1] += uu.x*ww.y;
            acc[0][2] += uu.x*ww.z; acc[0][3] += uu.x*ww.w;
            acc[1][0] += uu.y*ww.x; acc[1][1] += uu.y*ww.y;
            acc[1][2] += uu.y*ww.z; acc[1][3] += uu.y*ww.w;
        }
        __syncthreads();
    }

    const int ks = blockIdx.y;
#pragma unroll
    for (int bb = 0; bb < 2; bb++) {
        int b = tb*2 + bb;
#pragma unroll
        for (int nn = 0; nn < 4; nn++)
            part[(ks*B_ + b)*N + n0 + tn*4 + nn] = acc[bb][nn];
    }
}

// kh: h @ [Wh | Whh]^T, N=5120, K=1024, grid (80, 4), chunk 256
__global__ __launch_bounds__(256) void kh(const float* __restrict__ Wh,
                                          const float* __restrict__ Whh) {
    skinny_body<256>(d_h, Wh, Whh, 1024, N5, d_p5);
}
// kge: emb @ Wih^T, N=4096, K=1024, grid (64, 2), chunk 512
__global__ __launch_bounds__(256) void kge(const float* __restrict__ Wih) {
    skinny_body<512>(d_emb, Wih, Wih, 1 << 30, G4, d_gpart);
}

// ---------------------------------------------------------------------------
// kscore: score[b][p] = sum_h v[h]*tanh(xwx[t,b,p,h] + a[b,h] + b_att[h])
// grid (10, 32), 128 threads; a = sum of 4 kh partials (n < 1024).
// ---------------------------------------------------------------------------
__global__ __launch_bounds__(128) void kscore(
    int t, const float* __restrict__ b_att, const float* __restrict__ v)
{
    const int p = blockIdx.x, b = blockIdx.y, tid = threadIdx.x;
    const float* xw = &d_xwx[(size_t)((t*B_ + b)*P_ + p) * H_];

    float s = 0.0f;
#pragma unroll
    for (int j = 0; j < 8; j++) {
        int h = j*128 + tid;
        float a = b_att[h];
#pragma unroll
        for (int ks = 0; ks < 4; ks++) a += d_p5[(ks*B_ + b)*N5 + h];
        s += v[h] * tanh_fast(xw[h] + a);
    }
#pragma unroll
    for (int o = 16; o; o >>= 1) s += __shfl_xor_sync(0xffffffffu, s, o);
    __shared__ float red[4];
    int warp = tid >> 5, lane = tid & 31;
    if (lane == 0) red[warp] = s;
    __syncthreads();
    if (tid == 0)
        d_scores[b*P_ + p] = red[0] + red[1] + red[2] + red[3];
}

// ---------------------------------------------------------------------------
// kpool: softmax over P + attention pooling -> d_emb.
// float4 per thread; grid (2, 32), 128t.
// ---------------------------------------------------------------------------
__global__ __launch_bounds__(128) void kpool(int t, const float* __restrict__ x)
{
    const int b = blockIdx.y;
    const int i = (blockIdx.x * 128 + threadIdx.x) * 4;

    float sc[P_];
#pragma unroll
    for (int p = 0; p < P_; p++) sc[p] = d_scores[b*P_ + p];
    float mx = sc[0];
#pragma unroll
    for (int p = 1; p < P_; p++) mx = fmaxf(mx, sc[p]);
    float al[P_], ssum = 0.0f;
#pragma unroll
    for (int p = 0; p < P_; p++) { al[p] = expf(sc[p] - mx); ssum += al[p]; }
    float inv = 1.0f / ssum;

    const float* xb = &x[(size_t)((b*T_ + t)*P_) * I_ + i];
    float e0 = 0.0f, e1 = 0.0f, e2 = 0.0f, e3 = 0.0f;
#pragma unroll
    for (int p = 0; p < P_; p++) {
        float4 xv = *(const float4*)&xb[p*I_];
        e0 += al[p]*xv.x; e1 += al[p]*xv.y; e2 += al[p]*xv.z; e3 += al[p]*xv.w;
    }
    *(float4*)&d_emb[b*H_ + i] = make_float4(e0*inv, e1*inv, e2*inv, e3*inv);
}

// ---------------------------------------------------------------------------
// kcell: gates = gpart(2) + p5 gate slices(4) + biases -> cell + hidden
// ---------------------------------------------------------------------------
__global__ __launch_bounds__(256) void kcell(const float* __restrict__ bih,
                                             const float* __restrict__ bhh)
{
    int idx = blockIdx.x * 256 + threadIdx.x;   // 32768
    int b = idx >> 10, j = idx & 1023;
    float g4[4];
#pragma unroll
    for (int g = 0; g < 4; g++) {
        int m = g*H_ + j;
        float s = bih[m] + bhh[m];
#pragma unroll
        for (int ks = 0; ks < 2; ks++) s += d_gpart[(ks*B_ + b)*G4 + m];
#pragma unroll
        for (int ks = 0; ks < 4; ks++) s += d_p5[(ks*B_ + b)*N5 + 1024 + m];
        g4[g] = s;
    }
    float ig = sigmoidf(g4[0]);
    float fg = sigmoidf(g4[1]);
    float gg = tanhf(g4[2]);
    float og = sigmoidf(g4[3]);
    float cn = fg * d_c[idx] + ig * gg;
    d_c[idx] = cn;
    d_h[idx] = og * tanhf(cn);
}

// ---------------------------------------------------------------------------
// Final FC
// ---------------------------------------------------------------------------
__global__ __launch_bounds__(256) void kfc(const float* __restrict__ Wfc,
                                           const float* __restrict__ bfc,
                                           float* __restrict__ out)
{
    int b = blockIdx.x;
    int w = threadIdx.x >> 5;
    int lane = threadIdx.x & 31;
    const float* h = &d_h[b*H_];
    float acc = 0.0f;
    for (int i = lane; i < H_; i += 32) acc += h[i] * Wfc[w*H_ + i];
#pragma unroll
    for (int o = 16; o; o >>= 1) acc += __shfl_xor_sync(0xffffffffu, acc, o);
    if (lane == 0) out[b*C_ + w] = acc + bfc[w];
}

// ---------------------------------------------------------------------------
extern "C" void kernel_launch(void* const* d_in, const int* in_sizes, int n_in,
                              void* d_out, int out_size)
{
    const float* x    = (const float*)d_in[0];
    const float* Wx   = (const float*)d_in[1];
    const float* Wh   = (const float*)d_in[2];
    const float* batt = (const float*)d_in[3];
    const float* v    = (const float*)d_in[4];
    const float* Wih  = (const float*)d_in[5];
    const float* Whh  = (const float*)d_in[6];
    const float* bih  = (const float*)d_in[7];
    const float* bhh  = (const float*)d_in[8];
    const float* Wfc  = (const float*)d_in[9];
    const float* bfc  = (const float*)d_in[10];
    float* out = (float*)d_out;

    zero_state<<<128, 256>>>();
    sgemm_xwx<<<dim3(H_/128, M_/128), 256>>>(x, Wx);

    for (int t = 0; t < T_; t++) {
        kh<<<dim3(80, 4), 256>>>(Wh, Whh);
        kscore<<<dim3(P_, B_), 128>>>(t, batt, v);
        kpool<<<dim3(2, B_), 128>>>(t, x);
        kge<<<dim3(64, 2), 256>>>(Wih);
        kcell<<<128, 256>>>(bih, bhh);
    }
    kfc<<<32, 256>>>(Wfc, bfc, out);
}